// round 7
// baseline (speedup 1.0000x reference)
#include <cuda_runtime.h>
#include <cuda_fp16.h>
#include <cstdint>

// ---------------------------------------------------------------------------
// Problem dims
// ---------------------------------------------------------------------------
#define BB 8
#define UU 128
#define TT 256
#define EE 128
#define HH 128
#define NUM_TILES (BB * UU * 2)          // 2048 tiles of 128 t-rows each

// ---------------------------------------------------------------------------
// Device scratch (no allocs allowed)
// ---------------------------------------------------------------------------
__device__ __align__(16) float g_ue_proj[BB * UU * HH];     // ue @ W1u
__device__ __align__(16) float g_te_proj[BB * TT * HH];     // te @ W1t
__device__ __align__(16) float g_gcomb[BB * HH];            // ge @ W1g + b1
__device__ __align__(16) __half g_W2h[HH * HH];             // W2^T fp16 [n][k]
__device__ __align__(16) float2 g_tbl[768 * 4];             // gelu LUT, 4-way interleaved
__device__ int g_tile_ctr;

// ---------------------------------------------------------------------------
// PTX helpers (plain sm_103-safe: ldmatrix + mma.sync only)
// ---------------------------------------------------------------------------
__device__ __forceinline__ uint32_t smem_to_u32(const void* p) {
    uint32_t a;
    asm("{ .reg .u64 t; cvta.to.shared.u64 t, %1; cvt.u32.u64 %0, t; }"
        : "=r"(a) : "l"(p));
    return a;
}

__device__ __forceinline__ void ldmatrix_x4(uint32_t& r0, uint32_t& r1,
                                            uint32_t& r2, uint32_t& r3,
                                            uint32_t addr) {
    asm volatile("ldmatrix.sync.aligned.m8n8.x4.shared.b16 {%0,%1,%2,%3}, [%4];"
                 : "=r"(r0), "=r"(r1), "=r"(r2), "=r"(r3) : "r"(addr));
}

__device__ __forceinline__ void mma_fp16(float* c, const uint32_t* a,
                                         const uint32_t* b) {
    asm volatile(
        "mma.sync.aligned.m16n8k16.row.col.f32.f16.f16.f32 "
        "{%0,%1,%2,%3}, {%4,%5,%6,%7}, {%8,%9}, {%0,%1,%2,%3};"
        : "+f"(c[0]), "+f"(c[1]), "+f"(c[2]), "+f"(c[3])
        : "r"(a[0]), "r"(a[1]), "r"(a[2]), "r"(a[3]), "r"(b[0]), "r"(b[1]));
}

// ---------------------------------------------------------------------------
// Math helpers
// ---------------------------------------------------------------------------
__device__ __forceinline__ float gelu_f(float x) {
    return 0.5f * x * (1.0f + erff(x * 0.70710678118654752f));
}

// LUT gelu: PW-linear over [-6,6], 768 cells (h=1/64), 4-way bank-interleaved.
// Entry i for lane-group g lives at (4*i+g)*8 bytes -> disjoint bank subsets.
__device__ __forceinline__ float gelu_lut(float x, const char* tblb, int g4) {
    float u  = fmaf(x, 64.0f, 384.0f);
    u        = fminf(fmaxf(u, 0.0f), 767.98f);
    float fi = floorf(u);
    float fr = u - fi;
    int   i  = (int)fi;
    float2 e = *(const float2*)(tblb + ((i << 2) + g4) * 8);
    float y  = fmaf(e.y, fr, e.x);
    y = (x >= 6.0f) ? x : y;
    y = (x <= -6.0f) ? 0.0f : y;
    return y;
}

__device__ __forceinline__ uint32_t packh2(float a, float b) {
    __half2 h = __floats2half2_rn(a, b);
    return *reinterpret_cast<uint32_t*>(&h);
}

// ---------------------------------------------------------------------------
// Unified prep kernel, 394 blocks x 128 threads:
//   0..127   : ue rows (8/block)   -> g_ue_proj
//   128..383 : te rows (8/block)   -> g_te_proj
//   384      : ge rows (8) + b1    -> g_gcomb
//   385..392 : W2 fp16 transpose   -> g_W2h ([n][k])
//   393      : gelu LUT (4 replicas) + tile counter reset
// ---------------------------------------------------------------------------
__global__ __launch_bounds__(128) void prep_kernel(
    const float* __restrict__ ue, const float* __restrict__ te,
    const float* __restrict__ ge, const float* __restrict__ W1,
    const float* __restrict__ b1, const float* __restrict__ W2) {
    __shared__ float s_in[8 * EE];
    const int bid = blockIdx.x;
    const int tid = threadIdx.x;

    if (bid < 385) {
        const float* src;
        float* dst;
        const float* W;
        bool add_b1 = false;
        if (bid < 128) {
            src = ue + bid * 8 * EE;  dst = g_ue_proj + bid * 8 * HH;  W = W1;
        } else if (bid < 384) {
            int r = bid - 128;
            src = te + r * 8 * EE;    dst = g_te_proj + r * 8 * HH;
            W = W1 + EE * HH;
        } else {
            src = ge;  dst = g_gcomb;  W = W1 + 2 * EE * HH;  add_b1 = true;
        }
        for (int i = tid; i < 8 * EE; i += 128) s_in[i] = src[i];
        __syncthreads();

        float acc[8];
        float bb = add_b1 ? b1[tid] : 0.0f;
#pragma unroll
        for (int r = 0; r < 8; r++) acc[r] = bb;
#pragma unroll 4
        for (int e = 0; e < EE; e++) {
            float w = W[e * HH + tid];
#pragma unroll
            for (int r = 0; r < 8; r++)
                acc[r] = fmaf(s_in[r * EE + e], w, acc[r]);
        }
#pragma unroll
        for (int r = 0; r < 8; r++) dst[r * HH + tid] = acc[r];
    } else if (bid < 393) {
        int n0 = (bid - 385) * 16;
        for (int r = 0; r < 16; r++) {
            int n = n0 + r;
            g_W2h[n * HH + tid] = __float2half_rn(W2[tid * HH + n]);
        }
    } else {
        if (tid == 0) g_tile_ctr = 0;
        for (int i = tid; i < 768; i += 128) {
            float x0 = -6.0f + (float)i * (1.0f / 64.0f);
            float v0 = gelu_f(x0);
            float d  = gelu_f(x0 + (1.0f / 64.0f)) - v0;
            float2 e = make_float2(v0, d);
#pragma unroll
            for (int gg = 0; gg < 4; gg++) g_tbl[i * 4 + gg] = e;
        }
    }
}

// ---------------------------------------------------------------------------
// Main fused kernel (persistent, 8 warps/CTA, 2 CTAs/SM, fp16 HMMA):
//   per tile (b,u,thalf): h1 = gelu_lut(uc + te_proj) -> fp16 A in SMEM
//   -> D = A * W2h (fp32 accum in regs) -> +b2, gelu(erff), dot W3, +b3 -> out
// ---------------------------------------------------------------------------
static constexpr int ST      = 136;                 // row stride in fp16
static constexpr int STB     = ST * 2;              // 272 bytes
static constexpr int TILE_BY = 128 * STB;           // 34816
static constexpr int OFF_A   = 0;
static constexpr int OFF_B   = OFF_A + TILE_BY;     // 34816
static constexpr int OFF_TBL = OFF_B + TILE_BY;     // 69632 (128B aligned)
static constexpr int OFF_UC  = OFF_TBL + 24576;     // 94208: 128 floats
static constexpr int OFF_B2S = OFF_UC + 512;        // 128 floats
static constexpr int OFF_W3S = OFF_B2S + 512;       // 128 floats
static constexpr int OFF_PSUM = OFF_W3S + 512;      // 256 floats
static constexpr int OFF_TILE = OFF_PSUM + 1024;
static constexpr int SMEM_MAIN = OFF_TILE + 16;     // ~96.8 KB -> 2 CTAs/SM

__global__ __launch_bounds__(256, 2) void pairwise_main(
    const float* __restrict__ b2, const float* __restrict__ W3,
    const float* __restrict__ b3, float* __restrict__ out) {
    extern __shared__ char smem[];
    const uint32_t smem_base = smem_to_u32(smem);
    const int tid  = threadIdx.x;
    const int wid  = tid >> 5;
    const int lane = tid & 31;

    const char* tblb = smem + OFF_TBL;
    float* uc   = (float*)(smem + OFF_UC);
    float* b2s  = (float*)(smem + OFF_B2S);
    float* w3s  = (float*)(smem + OFF_W3S);
    float* psum = (float*)(smem + OFF_PSUM);
    int*   stile = (int*)(smem + OFF_TILE);

    // Stage W2 (padded rows) + LUT + b2/W3 into SMEM, once.
    {
        const uint4* sb = (const uint4*)g_W2h;
        for (int i = tid; i < 2048; i += 256) {       // 128 rows x 16 uint4
            int r = i >> 4, c = i & 15;
            *(uint4*)(smem + OFF_B + r * STB + c * 16) = sb[i];
        }
        const uint4* st = (const uint4*)g_tbl;
        for (int i = tid; i < 1536; i += 256)
            *((uint4*)(smem + OFF_TBL) + i) = st[i];
        if (tid < 128) { b2s[tid] = b2[tid]; w3s[tid] = W3[tid]; }
    }
    const float bias3 = b3[0];
    const int   g4    = lane & 3;                    // LUT bank group

    // Warp tiling: 4 (M) x 2 (N); each warp owns 32 rows x 64 cols.
    const int mwb   = (wid & 3) * 32;
    const int nh    = wid >> 2;
    const int nbase = nh * 64;

    // h1-stage mapping: 2 threads per row, 64 k-cols each (k-half warp-uniform)
    const int hrow = tid & 127;
    const int hkh  = (tid >> 7) * 64;

    // ldmatrix lane addressing
    const int a_r = mwb + (lane & 15);
    const int a_k = ((lane >> 4) & 1) * 8;
    // B x4: quad 0/1 -> n-tile even (k+0 / k+8); quad 2/3 -> n-tile odd
    const int b_r = nbase + ((lane >> 4) & 1) * 8 + (lane & 7);
    const int b_k = ((lane >> 3) & 1) * 8;

    __syncthreads();

    for (;;) {
        if (tid == 0) stile[0] = atomicAdd(&g_tile_ctr, 1);
        __syncthreads();
        const int tile = stile[0];
        if (tile >= NUM_TILES) break;

        const int b   = tile >> 8;
        const int rem = tile & 255;
        const int u   = rem >> 1;
        const int th  = rem & 1;

        // uc[k] = ue_proj[b,u,k] + (ge@W1g + b1)[b,k]
        if (tid < 128)
            uc[tid] = g_ue_proj[(b * UU + u) * HH + tid] + g_gcomb[b * HH + tid];
        __syncthreads();

        // ---- h1 stage: gelu_lut(te_proj + uc) -> fp16 A tile ----
        {
            const float* terow =
                g_te_proj + ((size_t)(b * TT + th * 128 + hrow)) * HH + hkh;
            const float* ucp = uc + hkh;
            char* arow = smem + OFF_A + hrow * STB + hkh * 2;
#pragma unroll
            for (int c8 = 0; c8 < 64; c8 += 8) {
                float4 t0 = *(const float4*)(terow + c8);
                float4 t1 = *(const float4*)(terow + c8 + 4);
                float4 u0 = *(const float4*)(ucp + c8);
                float4 u1 = *(const float4*)(ucp + c8 + 4);
                float v0 = gelu_lut(t0.x + u0.x, tblb, g4);
                float v1 = gelu_lut(t0.y + u0.y, tblb, g4);
                float v2 = gelu_lut(t0.z + u0.z, tblb, g4);
                float v3 = gelu_lut(t0.w + u0.w, tblb, g4);
                float v4 = gelu_lut(t1.x + u1.x, tblb, g4);
                float v5 = gelu_lut(t1.y + u1.y, tblb, g4);
                float v6 = gelu_lut(t1.z + u1.z, tblb, g4);
                float v7 = gelu_lut(t1.w + u1.w, tblb, g4);
                *(uint4*)(arow + c8 * 2) =
                    make_uint4(packh2(v0, v1), packh2(v2, v3),
                               packh2(v4, v5), packh2(v6, v7));
            }
        }
        __syncthreads();

        // ---- GEMM: D = A * W2h (fp32 accum in regs) ----
        float acc[2][8][4];
#pragma unroll
        for (int mt = 0; mt < 2; mt++)
#pragma unroll
            for (int nt = 0; nt < 8; nt++)
#pragma unroll
                for (int i = 0; i < 4; i++) acc[mt][nt][i] = 0.0f;

#pragma unroll
        for (int kt = 0; kt < 8; kt++) {
            const int k0 = kt * 16;
            uint32_t a[2][4];
#pragma unroll
            for (int mt = 0; mt < 2; mt++) {
                uint32_t aaddr =
                    smem_base + OFF_A + (a_r + mt * 16) * STB + (k0 + a_k) * 2;
                ldmatrix_x4(a[mt][0], a[mt][1], a[mt][2], a[mt][3], aaddr);
            }
            uint32_t bh[8][2];
#pragma unroll
            for (int np = 0; np < 4; np++) {          // pairs of n-tiles
                uint32_t baddr =
                    smem_base + OFF_B + (b_r + np * 16) * STB + (k0 + b_k) * 2;
                ldmatrix_x4(bh[np * 2][0], bh[np * 2][1],
                            bh[np * 2 + 1][0], bh[np * 2 + 1][1], baddr);
            }
#pragma unroll
            for (int mt = 0; mt < 2; mt++)
#pragma unroll
                for (int nt = 0; nt < 8; nt++)
                    mma_fp16(acc[mt][nt], a[mt], bh[nt]);
        }

        // ---- Epilogue: gelu(acc + b2) . W3 (erff path), reduce over N ----
        {
            float b2v[16], w3v[16];
#pragma unroll
            for (int nt = 0; nt < 8; nt++)
#pragma unroll
                for (int j = 0; j < 2; j++) {
                    int col = nbase + nt * 8 + 2 * (lane & 3) + j;
                    b2v[nt * 2 + j] = b2s[col];
                    w3v[nt * 2 + j] = w3s[col];
                }
#pragma unroll
            for (int mt = 0; mt < 2; mt++)
#pragma unroll
                for (int ih = 0; ih < 2; ih++) {
                    float s = 0.0f;
#pragma unroll
                    for (int nt = 0; nt < 8; nt++)
#pragma unroll
                        for (int j = 0; j < 2; j++) {
                            float v = acc[mt][nt][ih * 2 + j];
                            s = fmaf(gelu_f(v + b2v[nt * 2 + j]),
                                     w3v[nt * 2 + j], s);
                        }
                    s += __shfl_xor_sync(0xffffffffu, s, 1);
                    s += __shfl_xor_sync(0xffffffffu, s, 2);
                    if ((lane & 3) == 0) {
                        int row = mwb + mt * 16 + ih * 8 + (lane >> 2);
                        psum[nh * 128 + row] = s;
                    }
                }
        }
        __syncthreads();
        if (tid < 128) {
            out[(size_t)b * (UU * TT) + u * TT + th * 128 + tid] =
                psum[tid] + psum[128 + tid] + bias3;
        }
        __syncthreads();
    }
}

// ---------------------------------------------------------------------------
// Launch
// ---------------------------------------------------------------------------
extern "C" void kernel_launch(void* const* d_in, const int* in_sizes, int n_in,
                              void* d_out, int out_size) {
    (void)in_sizes; (void)n_in; (void)out_size;
    const float* ue = (const float*)d_in[0];
    const float* te = (const float*)d_in[1];
    const float* ge = (const float*)d_in[2];
    const float* W1 = (const float*)d_in[3];
    const float* b1 = (const float*)d_in[4];
    const float* W2 = (const float*)d_in[5];
    const float* b2 = (const float*)d_in[6];
    const float* W3 = (const float*)d_in[7];
    const float* b3 = (const float*)d_in[8];
    float* out = (float*)d_out;

    cudaFuncSetAttribute(pairwise_main,
                         cudaFuncAttributeMaxDynamicSharedMemorySize, SMEM_MAIN);

    prep_kernel<<<394, 128>>>(ue, te, ge, W1, b1, W2);
    pairwise_main<<<304, 256, SMEM_MAIN>>>(b2, W3, b3, out);
}

// round 8
// speedup vs baseline: 1.4375x; 1.4375x over previous
#include <cuda_runtime.h>
#include <cuda_fp16.h>
#include <cstdint>

// ---------------------------------------------------------------------------
// Problem dims
// ---------------------------------------------------------------------------
#define BB 8
#define UU 128
#define TT 256
#define EE 128
#define HH 128
#define NUM_TILES (BB * UU * 2)          // 2048 tiles of 128 t-rows each

// ---------------------------------------------------------------------------
// Device scratch (no allocs allowed)
// ---------------------------------------------------------------------------
__device__ __align__(16) float g_ue_proj[BB * UU * HH];     // ue @ W1u
__device__ __align__(16) float g_te_proj[BB * TT * HH];     // te @ W1t
__device__ __align__(16) float g_gcomb[BB * HH];            // ge @ W1g + b1
__device__ __align__(16) __half g_W2h[HH * HH];             // W2^T fp16 [n][k]
__device__ int g_tile_ctr;

// ---------------------------------------------------------------------------
// PTX helpers (plain sm_103-safe: ldmatrix + mma.sync only)
// ---------------------------------------------------------------------------
__device__ __forceinline__ uint32_t smem_to_u32(const void* p) {
    uint32_t a;
    asm("{ .reg .u64 t; cvta.to.shared.u64 t, %1; cvt.u32.u64 %0, t; }"
        : "=r"(a) : "l"(p));
    return a;
}

__device__ __forceinline__ void ldmatrix_x4(uint32_t& r0, uint32_t& r1,
                                            uint32_t& r2, uint32_t& r3,
                                            uint32_t addr) {
    asm volatile("ldmatrix.sync.aligned.m8n8.x4.shared.b16 {%0,%1,%2,%3}, [%4];"
                 : "=r"(r0), "=r"(r1), "=r"(r2), "=r"(r3) : "r"(addr));
}

__device__ __forceinline__ void mma_fp16(float* c, const uint32_t* a,
                                         const uint32_t* b) {
    asm volatile(
        "mma.sync.aligned.m16n8k16.row.col.f32.f16.f16.f32 "
        "{%0,%1,%2,%3}, {%4,%5,%6,%7}, {%8,%9}, {%0,%1,%2,%3};"
        : "+f"(c[0]), "+f"(c[1]), "+f"(c[2]), "+f"(c[3])
        : "r"(a[0]), "r"(a[1]), "r"(a[2]), "r"(a[3]), "r"(b[0]), "r"(b[1]));
}

// ---------------------------------------------------------------------------
// Math helpers
// ---------------------------------------------------------------------------
// Exact erf-based gelu (prep-side / reference use only)
__device__ __forceinline__ float gelu_exact(float x) {
    return 0.5f * x * (1.0f + erff(x * 0.70710678118654752f));
}

// Fast gelu: tanh-form via sigmoid, 2 MUFU + 5 FMA-pipe ops.
//   y = x * (1 - 1/(1 + 2^(c1*x + c2*x^3)))
//   c1 = 2*log2(e)*0.7978845608, c2 = c1*0.044715
// Tails: ex2->inf => y=x;  ex2->0 => y=0 (both correct).
__device__ __forceinline__ float gelu_f(float x) {
    float s = x * x;
    float p = fmaf(s, 0.1029433f, 2.3022084f);
    float z = x * p;
    float e;
    asm("ex2.approx.ftz.f32 %0, %1;" : "=f"(e) : "f"(z));
    float d = e + 1.0f;
    float r;
    asm("rcp.approx.ftz.f32 %0, %1;" : "=f"(r) : "f"(d));
    return fmaf(-x, r, x);
}

__device__ __forceinline__ uint32_t packh2(float a, float b) {
    __half2 h = __floats2half2_rn(a, b);
    return *reinterpret_cast<uint32_t*>(&h);
}

// ---------------------------------------------------------------------------
// Unified prep kernel, 394 blocks x 128 threads:
//   0..127   : ue rows (8/block)   -> g_ue_proj
//   128..383 : te rows (8/block)   -> g_te_proj
//   384      : ge rows (8) + b1    -> g_gcomb
//   385..392 : W2 fp16 transpose   -> g_W2h ([n][k])
//   393      : tile counter reset
// ---------------------------------------------------------------------------
__global__ __launch_bounds__(128) void prep_kernel(
    const float* __restrict__ ue, const float* __restrict__ te,
    const float* __restrict__ ge, const float* __restrict__ W1,
    const float* __restrict__ b1, const float* __restrict__ W2) {
    __shared__ float s_in[8 * EE];
    const int bid = blockIdx.x;
    const int tid = threadIdx.x;

    if (bid < 385) {
        const float* src;
        float* dst;
        const float* W;
        bool add_b1 = false;
        if (bid < 128) {
            src = ue + bid * 8 * EE;  dst = g_ue_proj + bid * 8 * HH;  W = W1;
        } else if (bid < 384) {
            int r = bid - 128;
            src = te + r * 8 * EE;    dst = g_te_proj + r * 8 * HH;
            W = W1 + EE * HH;
        } else {
            src = ge;  dst = g_gcomb;  W = W1 + 2 * EE * HH;  add_b1 = true;
        }
        for (int i = tid; i < 8 * EE; i += 128) s_in[i] = src[i];
        __syncthreads();

        float acc[8];
        float bb = add_b1 ? b1[tid] : 0.0f;
#pragma unroll
        for (int r = 0; r < 8; r++) acc[r] = bb;
#pragma unroll 4
        for (int e = 0; e < EE; e++) {
            float w = W[e * HH + tid];
#pragma unroll
            for (int r = 0; r < 8; r++)
                acc[r] = fmaf(s_in[r * EE + e], w, acc[r]);
        }
#pragma unroll
        for (int r = 0; r < 8; r++) dst[r * HH + tid] = acc[r];
    } else if (bid < 393) {
        int n0 = (bid - 385) * 16;
        for (int r = 0; r < 16; r++) {
            int n = n0 + r;
            g_W2h[n * HH + tid] = __float2half_rn(W2[tid * HH + n]);
        }
    } else {
        if (tid == 0) g_tile_ctr = 0;
    }
}

// ---------------------------------------------------------------------------
// Main fused kernel (persistent, 8 warps/CTA, 2 CTAs/SM, fp16 HMMA):
//   per tile (b,u,thalf): h1 = gelu(uc + te_proj) -> fp16 A in SMEM
//   -> D = A * W2h (fp32 accum in regs) -> +b2, gelu, dot W3, +b3 -> out
// ---------------------------------------------------------------------------
static constexpr int ST      = 136;                 // row stride in fp16
static constexpr int STB     = ST * 2;              // 272 bytes
static constexpr int TILE_BY = 128 * STB;           // 34816
static constexpr int OFF_A   = 0;
static constexpr int OFF_B   = OFF_A + TILE_BY;
static constexpr int OFF_UC  = OFF_B + TILE_BY;     // 128 floats
static constexpr int OFF_B2S = OFF_UC + 512;        // 128 floats
static constexpr int OFF_W3S = OFF_B2S + 512;       // 128 floats
static constexpr int OFF_PSUM = OFF_W3S + 512;      // 256 floats
static constexpr int OFF_TILE = OFF_PSUM + 1024;
static constexpr int SMEM_MAIN = OFF_TILE + 16;     // ~71.5 KB -> 2 CTAs/SM

__global__ __launch_bounds__(256, 2) void pairwise_main(
    const float* __restrict__ b2, const float* __restrict__ W3,
    const float* __restrict__ b3, float* __restrict__ out) {
    extern __shared__ char smem[];
    const uint32_t smem_base = smem_to_u32(smem);
    const int tid  = threadIdx.x;
    const int wid  = tid >> 5;
    const int lane = tid & 31;

    float* uc   = (float*)(smem + OFF_UC);
    float* b2s  = (float*)(smem + OFF_B2S);
    float* w3s  = (float*)(smem + OFF_W3S);
    float* psum = (float*)(smem + OFF_PSUM);
    int*   stile = (int*)(smem + OFF_TILE);

    // Stage W2 (padded rows) + b2/W3 into SMEM, once.
    {
        const uint4* sb = (const uint4*)g_W2h;
        for (int i = tid; i < 2048; i += 256) {       // 128 rows x 16 uint4
            int r = i >> 4, c = i & 15;
            *(uint4*)(smem + OFF_B + r * STB + c * 16) = sb[i];
        }
        if (tid < 128) { b2s[tid] = b2[tid]; w3s[tid] = W3[tid]; }
    }
    const float bias3 = b3[0];

    // Warp tiling: 4 (M) x 2 (N); each warp owns 32 rows x 64 cols.
    const int mwb   = (wid & 3) * 32;
    const int nh    = wid >> 2;
    const int nbase = nh * 64;

    // h1-stage mapping: 2 threads per row, 64 k-cols each (k-half warp-uniform)
    const int hrow = tid & 127;
    const int hkh  = (tid >> 7) * 64;

    // ldmatrix lane addressing
    const int a_r = mwb + (lane & 15);
    const int a_k = ((lane >> 4) & 1) * 8;
    // B x4: quad 0/1 -> n-tile even (k+0 / k+8); quad 2/3 -> n-tile odd
    const int b_r = nbase + ((lane >> 4) & 1) * 8 + (lane & 7);
    const int b_k = ((lane >> 3) & 1) * 8;

    __syncthreads();

    for (;;) {
        if (tid == 0) stile[0] = atomicAdd(&g_tile_ctr, 1);
        __syncthreads();
        const int tile = stile[0];
        if (tile >= NUM_TILES) break;

        const int b   = tile >> 8;
        const int rem = tile & 255;
        const int u   = rem >> 1;
        const int th  = rem & 1;

        // uc[k] = ue_proj[b,u,k] + (ge@W1g + b1)[b,k]
        if (tid < 128)
            uc[tid] = g_ue_proj[(b * UU + u) * HH + tid] + g_gcomb[b * HH + tid];
        __syncthreads();

        // ---- h1 stage: gelu(te_proj + uc) -> fp16 A tile ----
        {
            const float* terow =
                g_te_proj + ((size_t)(b * TT + th * 128 + hrow)) * HH + hkh;
            const float* ucp = uc + hkh;
            char* arow = smem + OFF_A + hrow * STB + hkh * 2;
#pragma unroll
            for (int c8 = 0; c8 < 64; c8 += 8) {
                float4 t0 = *(const float4*)(terow + c8);
                float4 t1 = *(const float4*)(terow + c8 + 4);
                float4 u0 = *(const float4*)(ucp + c8);
                float4 u1 = *(const float4*)(ucp + c8 + 4);
                float v0 = gelu_f(t0.x + u0.x);
                float v1 = gelu_f(t0.y + u0.y);
                float v2 = gelu_f(t0.z + u0.z);
                float v3 = gelu_f(t0.w + u0.w);
                float v4 = gelu_f(t1.x + u1.x);
                float v5 = gelu_f(t1.y + u1.y);
                float v6 = gelu_f(t1.z + u1.z);
                float v7 = gelu_f(t1.w + u1.w);
                *(uint4*)(arow + c8 * 2) =
                    make_uint4(packh2(v0, v1), packh2(v2, v3),
                               packh2(v4, v5), packh2(v6, v7));
            }
        }
        __syncthreads();

        // ---- GEMM: D = A * W2h (fp32 accum in regs) ----
        float acc[2][8][4];
#pragma unroll
        for (int mt = 0; mt < 2; mt++)
#pragma unroll
            for (int nt = 0; nt < 8; nt++)
#pragma unroll
                for (int i = 0; i < 4; i++) acc[mt][nt][i] = 0.0f;

#pragma unroll
        for (int kt = 0; kt < 8; kt++) {
            const int k0 = kt * 16;
            uint32_t a[2][4];
#pragma unroll
            for (int mt = 0; mt < 2; mt++) {
                uint32_t aaddr =
                    smem_base + OFF_A + (a_r + mt * 16) * STB + (k0 + a_k) * 2;
                ldmatrix_x4(a[mt][0], a[mt][1], a[mt][2], a[mt][3], aaddr);
            }
            uint32_t bh[8][2];
#pragma unroll
            for (int np = 0; np < 4; np++) {          // pairs of n-tiles
                uint32_t baddr =
                    smem_base + OFF_B + (b_r + np * 16) * STB + (k0 + b_k) * 2;
                ldmatrix_x4(bh[np * 2][0], bh[np * 2][1],
                            bh[np * 2 + 1][0], bh[np * 2 + 1][1], baddr);
            }
#pragma unroll
            for (int mt = 0; mt < 2; mt++)
#pragma unroll
                for (int nt = 0; nt < 8; nt++)
                    mma_fp16(acc[mt][nt], a[mt], bh[nt]);
        }

        // ---- Epilogue: gelu(acc + b2) . W3, reduce over N ----
        {
            float b2v[16], w3v[16];
#pragma unroll
            for (int nt = 0; nt < 8; nt++)
#pragma unroll
                for (int j = 0; j < 2; j++) {
                    int col = nbase + nt * 8 + 2 * (lane & 3) + j;
                    b2v[nt * 2 + j] = b2s[col];
                    w3v[nt * 2 + j] = w3s[col];
                }
#pragma unroll
            for (int mt = 0; mt < 2; mt++)
#pragma unroll
                for (int ih = 0; ih < 2; ih++) {
                    float s = 0.0f;
#pragma unroll
                    for (int nt = 0; nt < 8; nt++)
#pragma unroll
                        for (int j = 0; j < 2; j++) {
                            float v = acc[mt][nt][ih * 2 + j];
                            s = fmaf(gelu_f(v + b2v[nt * 2 + j]),
                                     w3v[nt * 2 + j], s);
                        }
                    s += __shfl_xor_sync(0xffffffffu, s, 1);
                    s += __shfl_xor_sync(0xffffffffu, s, 2);
                    if ((lane & 3) == 0) {
                        int row = mwb + mt * 16 + ih * 8 + (lane >> 2);
                        psum[nh * 128 + row] = s;
                    }
                }
        }
        __syncthreads();
        if (tid < 128) {
            out[(size_t)b * (UU * TT) + u * TT + th * 128 + tid] =
                psum[tid] + psum[128 + tid] + bias3;
        }
        __syncthreads();
    }
}

// ---------------------------------------------------------------------------
// Launch
// ---------------------------------------------------------------------------
extern "C" void kernel_launch(void* const* d_in, const int* in_sizes, int n_in,
                              void* d_out, int out_size) {
    (void)in_sizes; (void)n_in; (void)out_size;
    const float* ue = (const float*)d_in[0];
    const float* te = (const float*)d_in[1];
    const float* ge = (const float*)d_in[2];
    const float* W1 = (const float*)d_in[3];
    const float* b1 = (const float*)d_in[4];
    const float* W2 = (const float*)d_in[5];
    const float* b2 = (const float*)d_in[6];
    const float* W3 = (const float*)d_in[7];
    const float* b3 = (const float*)d_in[8];
    float* out = (float*)d_out;

    cudaFuncSetAttribute(pairwise_main,
                         cudaFuncAttributeMaxDynamicSharedMemorySize, SMEM_MAIN);

    prep_kernel<<<394, 128>>>(ue, te, ge, W1, b1, W2);
    pairwise_main<<<304, 256, SMEM_MAIN>>>(b2, W3, b3, out);
}

// round 9
// speedup vs baseline: 1.8808x; 1.3084x over previous
#include <cuda_runtime.h>
#include <cuda_fp16.h>
#include <cstdint>

// ---------------------------------------------------------------------------
// Problem dims
// ---------------------------------------------------------------------------
#define BB 8
#define UU 128
#define TT 256
#define EE 128
#define HH 128
#define NUM_TILES (BB * UU * 2)          // 2048 tiles of 128 t-rows each

// ---------------------------------------------------------------------------
// Device scratch (no allocs allowed)
// ---------------------------------------------------------------------------
__device__ __align__(16) float g_ue_proj[BB * UU * HH];     // ue @ W1u
__device__ __align__(16) float g_te_proj[BB * TT * HH];     // te @ W1t
__device__ __align__(16) float g_gcomb[BB * HH];            // ge @ W1g + b1
__device__ __align__(16) __half g_W2h[HH * HH];             // W2^T fp16 [n][k]
__device__ int g_tile_ctr;

// ---------------------------------------------------------------------------
// PTX helpers (plain sm_103-safe: ldmatrix + mma.sync only)
// ---------------------------------------------------------------------------
__device__ __forceinline__ uint32_t smem_to_u32(const void* p) {
    uint32_t a;
    asm("{ .reg .u64 t; cvta.to.shared.u64 t, %1; cvt.u32.u64 %0, t; }"
        : "=r"(a) : "l"(p));
    return a;
}

__device__ __forceinline__ void ldmatrix_x4(uint32_t& r0, uint32_t& r1,
                                            uint32_t& r2, uint32_t& r3,
                                            uint32_t addr) {
    asm volatile("ldmatrix.sync.aligned.m8n8.x4.shared.b16 {%0,%1,%2,%3}, [%4];"
                 : "=r"(r0), "=r"(r1), "=r"(r2), "=r"(r3) : "r"(addr));
}

__device__ __forceinline__ void mma_fp16(float* c, const uint32_t* a,
                                         const uint32_t* b) {
    asm volatile(
        "mma.sync.aligned.m16n8k16.row.col.f32.f16.f16.f32 "
        "{%0,%1,%2,%3}, {%4,%5,%6,%7}, {%8,%9}, {%0,%1,%2,%3};"
        : "+f"(c[0]), "+f"(c[1]), "+f"(c[2]), "+f"(c[3])
        : "r"(a[0]), "r"(a[1]), "r"(a[2]), "r"(a[3]), "r"(b[0]), "r"(b[1]));
}

// ---------------------------------------------------------------------------
// Math helpers
// ---------------------------------------------------------------------------
// Fast gelu: tanh-form via sigmoid, 2 MUFU + ~5 FMA-pipe ops.
//   y = x * (1 - 1/(1 + 2^(c1*x + c2*x^3)))
__device__ __forceinline__ float gelu_f(float x) {
    float s = x * x;
    float p = fmaf(s, 0.1029433f, 2.3022084f);
    float z = x * p;
    float e;
    asm("ex2.approx.ftz.f32 %0, %1;" : "=f"(e) : "f"(z));
    float d = e + 1.0f;
    float r;
    asm("rcp.approx.ftz.f32 %0, %1;" : "=f"(r) : "f"(d));
    return fmaf(-x, r, x);
}

__device__ __forceinline__ uint32_t packh2(float a, float b) {
    __half2 h = __floats2half2_rn(a, b);
    return *reinterpret_cast<uint32_t*>(&h);
}

// ---------------------------------------------------------------------------
// Unified prep kernel, 394 blocks x 128 threads:
//   0..127   : ue rows (8/block)   -> g_ue_proj
//   128..383 : te rows (8/block)   -> g_te_proj
//   384      : ge rows (8) + b1    -> g_gcomb
//   385..392 : W2 fp16 transpose   -> g_W2h ([n][k])
//   393      : tile counter reset
// ---------------------------------------------------------------------------
__global__ __launch_bounds__(128) void prep_kernel(
    const float* __restrict__ ue, const float* __restrict__ te,
    const float* __restrict__ ge, const float* __restrict__ W1,
    const float* __restrict__ b1, const float* __restrict__ W2) {
    __shared__ float s_in[8 * EE];
    const int bid = blockIdx.x;
    const int tid = threadIdx.x;

    if (bid < 385) {
        const float* src;
        float* dst;
        const float* W;
        bool add_b1 = false;
        if (bid < 128) {
            src = ue + bid * 8 * EE;  dst = g_ue_proj + bid * 8 * HH;  W = W1;
        } else if (bid < 384) {
            int r = bid - 128;
            src = te + r * 8 * EE;    dst = g_te_proj + r * 8 * HH;
            W = W1 + EE * HH;
        } else {
            src = ge;  dst = g_gcomb;  W = W1 + 2 * EE * HH;  add_b1 = true;
        }
        for (int i = tid; i < 8 * EE; i += 128) s_in[i] = src[i];
        __syncthreads();

        float acc[8];
        float bb = add_b1 ? b1[tid] : 0.0f;
#pragma unroll
        for (int r = 0; r < 8; r++) acc[r] = bb;
#pragma unroll 4
        for (int e = 0; e < EE; e++) {
            float w = W[e * HH + tid];
#pragma unroll
            for (int r = 0; r < 8; r++)
                acc[r] = fmaf(s_in[r * EE + e], w, acc[r]);
        }
#pragma unroll
        for (int r = 0; r < 8; r++) dst[r * HH + tid] = acc[r];
    } else if (bid < 393) {
        int n0 = (bid - 385) * 16;
        for (int r = 0; r < 16; r++) {
            int n = n0 + r;
            g_W2h[n * HH + tid] = __float2half_rn(W2[tid * HH + n]);
        }
    } else {
        if (tid == 0) g_tile_ctr = 0;
    }
}

// ---------------------------------------------------------------------------
// Main fused kernel (persistent, 8 warps/CTA, 2 CTAs/SM, fp16 HMMA):
//   per tile (b,u,thalf): h1 = gelu(uc + te_proj) -> fp16 A in SMEM (coalesced)
//   -> D = A * W2h (fp32 accum in regs) -> +b2, gelu, dot W3, +b3 -> out
// ---------------------------------------------------------------------------
static constexpr int ST      = 136;                 // row stride in fp16
static constexpr int STB     = ST * 2;              // 272 bytes
static constexpr int TILE_BY = 128 * STB;           // 34816
static constexpr int OFF_A   = 0;
static constexpr int OFF_B   = OFF_A + TILE_BY;
static constexpr int OFF_UC  = OFF_B + TILE_BY;     // 128 floats
static constexpr int OFF_B2S = OFF_UC + 512;        // 128 floats
static constexpr int OFF_W3S = OFF_B2S + 512;       // 128 floats
static constexpr int OFF_PSUM = OFF_W3S + 512;      // 256 floats
static constexpr int OFF_TILE = OFF_PSUM + 1024;
static constexpr int SMEM_MAIN = OFF_TILE + 16;     // ~71.5 KB -> 2 CTAs/SM

__global__ __launch_bounds__(256, 2) void pairwise_main(
    const float* __restrict__ b2, const float* __restrict__ W3,
    const float* __restrict__ b3, float* __restrict__ out) {
    extern __shared__ char smem[];
    const uint32_t smem_base = smem_to_u32(smem);
    const int tid  = threadIdx.x;
    const int wid  = tid >> 5;
    const int lane = tid & 31;

    float* uc   = (float*)(smem + OFF_UC);
    float* b2s  = (float*)(smem + OFF_B2S);
    float* w3s  = (float*)(smem + OFF_W3S);
    float* psum = (float*)(smem + OFF_PSUM);
    int*   stile = (int*)(smem + OFF_TILE);

    // Stage W2 (padded rows) + b2/W3 into SMEM, once.
    {
        const uint4* sb = (const uint4*)g_W2h;
        for (int i = tid; i < 2048; i += 256) {       // 128 rows x 16 uint4
            int r = i >> 4, c = i & 15;
            *(uint4*)(smem + OFF_B + r * STB + c * 16) = sb[i];
        }
        if (tid < 128) { b2s[tid] = b2[tid]; w3s[tid] = W3[tid]; }
    }
    const float bias3 = b3[0];

    // Warp tiling: 4 (M) x 2 (N); each warp owns 32 rows x 64 cols.
    const int mwb   = (wid & 3) * 32;
    const int nh    = wid >> 2;
    const int nbase = nh * 64;

    // ldmatrix lane addressing
    const int a_r = mwb + (lane & 15);
    const int a_k = ((lane >> 4) & 1) * 8;
    // B x4: quad 0/1 -> n-tile even (k+0 / k+8); quad 2/3 -> n-tile odd
    const int b_r = nbase + ((lane >> 4) & 1) * 8 + (lane & 7);
    const int b_k = ((lane >> 3) & 1) * 8;

    __syncthreads();

    for (;;) {
        if (tid == 0) stile[0] = atomicAdd(&g_tile_ctr, 1);
        __syncthreads();
        const int tile = stile[0];
        if (tile >= NUM_TILES) break;

        const int b   = tile >> 8;
        const int rem = tile & 255;
        const int u   = rem >> 1;
        const int th  = rem & 1;

        // uc[k] = ue_proj[b,u,k] + (ge@W1g + b1)[b,k]
        if (tid < 128)
            uc[tid] = g_ue_proj[(b * UU + u) * HH + tid] + g_gcomb[b * HH + tid];
        __syncthreads();

        // ---- h1 stage (coalesced): gelu(te_proj + uc) -> fp16 A tile ----
        // lane l owns cols 4l..4l+3 for every row; warp w rows {w, w+8, ...}.
        {
            const float4 ucv = *(const float4*)(uc + (lane << 2));
            const float* tebase =
                g_te_proj + ((size_t)(b * TT + th * 128)) * HH + (lane << 2);
            char* abase = smem + OFF_A + lane * 8;
#pragma unroll
            for (int r8 = 0; r8 < 16; r8++) {
                const int row = wid + (r8 << 3);
                float4 tv = *(const float4*)(tebase + (size_t)row * HH);
                float v0 = gelu_f(tv.x + ucv.x);
                float v1 = gelu_f(tv.y + ucv.y);
                float v2 = gelu_f(tv.z + ucv.z);
                float v3 = gelu_f(tv.w + ucv.w);
                *(uint2*)(abase + row * STB) =
                    make_uint2(packh2(v0, v1), packh2(v2, v3));
            }
        }
        __syncthreads();

        // ---- GEMM: D = A * W2h (fp32 accum in regs) ----
        float acc[2][8][4];
#pragma unroll
        for (int mt = 0; mt < 2; mt++)
#pragma unroll
            for (int nt = 0; nt < 8; nt++)
#pragma unroll
                for (int i = 0; i < 4; i++) acc[mt][nt][i] = 0.0f;

#pragma unroll
        for (int kt = 0; kt < 8; kt++) {
            const int k0 = kt * 16;
            uint32_t a[2][4];
#pragma unroll
            for (int mt = 0; mt < 2; mt++) {
                uint32_t aaddr =
                    smem_base + OFF_A + (a_r + mt * 16) * STB + (k0 + a_k) * 2;
                ldmatrix_x4(a[mt][0], a[mt][1], a[mt][2], a[mt][3], aaddr);
            }
            uint32_t bh[8][2];
#pragma unroll
            for (int np = 0; np < 4; np++) {          // pairs of n-tiles
                uint32_t baddr =
                    smem_base + OFF_B + (b_r + np * 16) * STB + (k0 + b_k) * 2;
                ldmatrix_x4(bh[np * 2][0], bh[np * 2][1],
                            bh[np * 2 + 1][0], bh[np * 2 + 1][1], baddr);
            }
#pragma unroll
            for (int mt = 0; mt < 2; mt++)
#pragma unroll
                for (int nt = 0; nt < 8; nt++)
                    mma_fp16(acc[mt][nt], a[mt], bh[nt]);
        }

        // ---- Epilogue: gelu(acc + b2) . W3, reduce over N ----
        {
            float b2v[16], w3v[16];
#pragma unroll
            for (int nt = 0; nt < 8; nt++)
#pragma unroll
                for (int j = 0; j < 2; j++) {
                    int col = nbase + nt * 8 + 2 * (lane & 3) + j;
                    b2v[nt * 2 + j] = b2s[col];
                    w3v[nt * 2 + j] = w3s[col];
                }
#pragma unroll
            for (int mt = 0; mt < 2; mt++)
#pragma unroll
                for (int ih = 0; ih < 2; ih++) {
                    float s = 0.0f;
#pragma unroll
                    for (int nt = 0; nt < 8; nt++)
#pragma unroll
                        for (int j = 0; j < 2; j++) {
                            float v = acc[mt][nt][ih * 2 + j];
                            s = fmaf(gelu_f(v + b2v[nt * 2 + j]),
                                     w3v[nt * 2 + j], s);
                        }
                    s += __shfl_xor_sync(0xffffffffu, s, 1);
                    s += __shfl_xor_sync(0xffffffffu, s, 2);
                    if ((lane & 3) == 0) {
                        int row = mwb + mt * 16 + ih * 8 + (lane >> 2);
                        psum[nh * 128 + row] = s;
                    }
                }
        }
        __syncthreads();
        if (tid < 128) {
            out[(size_t)b * (UU * TT) + u * TT + th * 128 + tid] =
                psum[tid] + psum[128 + tid] + bias3;
        }
        __syncthreads();
    }
}

// ---------------------------------------------------------------------------
// Launch
// ---------------------------------------------------------------------------
extern "C" void kernel_launch(void* const* d_in, const int* in_sizes, int n_in,
                              void* d_out, int out_size) {
    (void)in_sizes; (void)n_in; (void)out_size;
    const float* ue = (const float*)d_in[0];
    const float* te = (const float*)d_in[1];
    const float* ge = (const float*)d_in[2];
    const float* W1 = (const float*)d_in[3];
    const float* b1 = (const float*)d_in[4];
    const float* W2 = (const float*)d_in[5];
    const float* b2 = (const float*)d_in[6];
    const float* W3 = (const float*)d_in[7];
    const float* b3 = (const float*)d_in[8];
    float* out = (float*)d_out;

    cudaFuncSetAttribute(pairwise_main,
                         cudaFuncAttributeMaxDynamicSharedMemorySize, SMEM_MAIN);

    prep_kernel<<<394, 128>>>(ue, te, ge, W1, b1, W2);
    pairwise_main<<<304, 256, SMEM_MAIN>>>(b2, W3, b3, out);
}

// round 10
// speedup vs baseline: 2.0178x; 1.0728x over previous
#include <cuda_runtime.h>
#include <cuda_fp16.h>
#include <cstdint>

// ---------------------------------------------------------------------------
// Problem dims
// ---------------------------------------------------------------------------
#define BB 8
#define UU 128
#define TT 256
#define EE 128
#define HH 128
#define NUM_STRIPS (BB * UU * 16)        // 16384 strips of 16 t-rows

// ---------------------------------------------------------------------------
// Device scratch (no allocs allowed)
// ---------------------------------------------------------------------------
__device__ __align__(16) float g_ue_proj[BB * UU * HH];     // ue @ W1u
__device__ __align__(16) float g_te_proj[BB * TT * HH];     // te @ W1t
__device__ __align__(16) float g_gcomb[BB * HH];            // ge @ W1g + b1
__device__ __align__(16) __half g_W2h[HH * HH];             // W2^T fp16 [n][k]
__device__ int g_tile_ctr;

// ---------------------------------------------------------------------------
// PTX helpers (plain sm_103-safe: ldmatrix + mma.sync only)
// ---------------------------------------------------------------------------
__device__ __forceinline__ uint32_t smem_to_u32(const void* p) {
    uint32_t a;
    asm("{ .reg .u64 t; cvta.to.shared.u64 t, %1; cvt.u32.u64 %0, t; }"
        : "=r"(a) : "l"(p));
    return a;
}

__device__ __forceinline__ void ldmatrix_x4(uint32_t& r0, uint32_t& r1,
                                            uint32_t& r2, uint32_t& r3,
                                            uint32_t addr) {
    asm volatile("ldmatrix.sync.aligned.m8n8.x4.shared.b16 {%0,%1,%2,%3}, [%4];"
                 : "=r"(r0), "=r"(r1), "=r"(r2), "=r"(r3) : "r"(addr));
}

__device__ __forceinline__ void mma_fp16(float* c, const uint32_t* a,
                                         const uint32_t* b) {
    asm volatile(
        "mma.sync.aligned.m16n8k16.row.col.f32.f16.f16.f32 "
        "{%0,%1,%2,%3}, {%4,%5,%6,%7}, {%8,%9}, {%0,%1,%2,%3};"
        : "+f"(c[0]), "+f"(c[1]), "+f"(c[2]), "+f"(c[3])
        : "r"(a[0]), "r"(a[1]), "r"(a[2]), "r"(a[3]), "r"(b[0]), "r"(b[1]));
}

// ---------------------------------------------------------------------------
// Math helpers
// ---------------------------------------------------------------------------
// Fast gelu: tanh-form via sigmoid, 2 MUFU + ~5 FMA-pipe ops.
//   y = x * (1 - 1/(1 + 2^(c1*x + c2*x^3)))
__device__ __forceinline__ float gelu_f(float x) {
    float s = x * x;
    float p = fmaf(s, 0.1029433f, 2.3022084f);
    float z = x * p;
    float e;
    asm("ex2.approx.ftz.f32 %0, %1;" : "=f"(e) : "f"(z));
    float d = e + 1.0f;
    float r;
    asm("rcp.approx.ftz.f32 %0, %1;" : "=f"(r) : "f"(d));
    return fmaf(-x, r, x);
}

__device__ __forceinline__ uint32_t packh2(float a, float b) {
    __half2 h = __floats2half2_rn(a, b);
    return *reinterpret_cast<uint32_t*>(&h);
}

// ---------------------------------------------------------------------------
// Unified prep kernel, 394 blocks x 128 threads (unchanged from R9)
// ---------------------------------------------------------------------------
__global__ __launch_bounds__(128) void prep_kernel(
    const float* __restrict__ ue, const float* __restrict__ te,
    const float* __restrict__ ge, const float* __restrict__ W1,
    const float* __restrict__ b1, const float* __restrict__ W2) {
    __shared__ float s_in[8 * EE];
    const int bid = blockIdx.x;
    const int tid = threadIdx.x;

    if (bid < 385) {
        const float* src;
        float* dst;
        const float* W;
        bool add_b1 = false;
        if (bid < 128) {
            src = ue + bid * 8 * EE;  dst = g_ue_proj + bid * 8 * HH;  W = W1;
        } else if (bid < 384) {
            int r = bid - 128;
            src = te + r * 8 * EE;    dst = g_te_proj + r * 8 * HH;
            W = W1 + EE * HH;
        } else {
            src = ge;  dst = g_gcomb;  W = W1 + 2 * EE * HH;  add_b1 = true;
        }
        for (int i = tid; i < 8 * EE; i += 128) s_in[i] = src[i];
        __syncthreads();

        float acc[8];
        float bb = add_b1 ? b1[tid] : 0.0f;
#pragma unroll
        for (int r = 0; r < 8; r++) acc[r] = bb;
#pragma unroll 4
        for (int e = 0; e < EE; e++) {
            float w = W[e * HH + tid];
#pragma unroll
            for (int r = 0; r < 8; r++)
                acc[r] = fmaf(s_in[r * EE + e], w, acc[r]);
        }
#pragma unroll
        for (int r = 0; r < 8; r++) dst[r * HH + tid] = acc[r];
    } else if (bid < 393) {
        int n0 = (bid - 385) * 16;
        for (int r = 0; r < 16; r++) {
            int n = n0 + r;
            g_W2h[n * HH + tid] = __float2half_rn(W2[tid * HH + n]);
        }
    } else {
        if (tid == 0) g_tile_ctr = 0;
    }
}

// ---------------------------------------------------------------------------
// Main fused kernel — warp-autonomous strips, NO block barriers in the loop.
// Each warp: steal strip (b,u,tq) -> h1 gelu into private 16-row A buffer ->
// syncwarp -> 16x128x128 warp GEMM vs shared W2 -> epilogue -> direct STG.
// ---------------------------------------------------------------------------
static constexpr int ST      = 136;                 // row stride in fp16
static constexpr int STB     = ST * 2;              // 272 bytes
static constexpr int OFF_B   = 0;                   // 128 rows x STB = 34816
static constexpr int OFF_A   = 34816;               // 8 warps x 16 rows x STB
static constexpr int OFF_BW  = OFF_A + 34816;       // 128 x float2 (b2, W3)
static constexpr int SMEM_MAIN = OFF_BW + 1024;     // ~70.7 KB -> 2 CTAs/SM

__global__ __launch_bounds__(256, 2) void pairwise_main(
    const float* __restrict__ b2, const float* __restrict__ W3,
    const float* __restrict__ b3, float* __restrict__ out) {
    extern __shared__ char smem[];
    const uint32_t smem_base = smem_to_u32(smem);
    const int tid  = threadIdx.x;
    const int wid  = tid >> 5;
    const int lane = tid & 31;

    // Stage W2 (padded rows) + packed (b2, W3) pairs into SMEM, once.
    {
        const uint4* sb = (const uint4*)g_W2h;
        for (int i = tid; i < 2048; i += 256) {       // 128 rows x 16 uint4
            int r = i >> 4, c = i & 15;
            *(uint4*)(smem + OFF_B + r * STB + c * 16) = sb[i];
        }
        if (tid < 128)
            *(float2*)(smem + OFF_BW + tid * 8) = make_float2(b2[tid], W3[tid]);
    }
    const float bias3 = b3[0];
    __syncthreads();                                 // the only block barrier

    // Per-warp A buffer base
    const uint32_t abase_u = smem_base + OFF_A + wid * 16 * STB;
    char* abuf = smem + OFF_A + wid * 16 * STB + lane * 8;

    // ldmatrix lane addressing (within warp-private 16-row A / shared B)
    const uint32_t a_addr0 = abase_u + (lane & 15) * STB + ((lane >> 4) * 8) * 2;
    const int b_r = ((lane >> 4) & 1) * 8 + (lane & 7);
    const int b_k = ((lane >> 3) & 1) * 8;

    for (;;) {
        int s;
        if (lane == 0) s = atomicAdd(&g_tile_ctr, 1);
        s = __shfl_sync(0xffffffffu, s, 0);
        if (s >= NUM_STRIPS) break;

        const int b  = s >> 11;
        const int u  = (s >> 4) & 127;
        const int tq = s & 15;

        // per-lane uc columns 4l..4l+3 (registers; no smem, no barrier)
        const float4 uev = *(const float4*)(g_ue_proj + (b * UU + u) * HH + (lane << 2));
        const float4 gcv = *(const float4*)(g_gcomb + b * HH + (lane << 2));
        const float4 ucv = make_float4(uev.x + gcv.x, uev.y + gcv.y,
                                       uev.z + gcv.z, uev.w + gcv.w);

        // ---- h1: 16 rows, coalesced LDG + gelu -> warp-private A ----
        const float* tebase =
            g_te_proj + ((size_t)(b * TT + tq * 16)) * HH + (lane << 2);
#pragma unroll
        for (int r = 0; r < 16; r++) {
            float4 tv = *(const float4*)(tebase + (size_t)r * HH);
            float v0 = gelu_f(tv.x + ucv.x);
            float v1 = gelu_f(tv.y + ucv.y);
            float v2 = gelu_f(tv.z + ucv.z);
            float v3 = gelu_f(tv.w + ucv.w);
            *(uint2*)(abuf + r * STB) = make_uint2(packh2(v0, v1), packh2(v2, v3));
        }
        __syncwarp();

        // ---- GEMM: 16x128x128, acc[16 n-tiles][4] in regs ----
        float acc[16][4];
#pragma unroll
        for (int nt = 0; nt < 16; nt++)
#pragma unroll
            for (int i = 0; i < 4; i++) acc[nt][i] = 0.0f;

#pragma unroll
        for (int kt = 0; kt < 8; kt++) {
            const int k0 = kt * 16;
            uint32_t a[4];
            ldmatrix_x4(a[0], a[1], a[2], a[3], a_addr0 + k0 * 2);
            uint32_t bh[16][2];
#pragma unroll
            for (int np = 0; np < 8; np++) {          // pairs of n-tiles
                uint32_t baddr =
                    smem_base + OFF_B + (b_r + np * 16) * STB + (k0 + b_k) * 2;
                ldmatrix_x4(bh[np * 2][0], bh[np * 2][1],
                            bh[np * 2 + 1][0], bh[np * 2 + 1][1], baddr);
            }
#pragma unroll
            for (int nt = 0; nt < 16; nt++)
                mma_fp16(acc[nt], a, bh[nt]);
        }

        // ---- Epilogue: gelu(acc + b2) . W3 over N=128, direct STG ----
        float s0 = 0.0f, s1 = 0.0f;
#pragma unroll
        for (int nt = 0; nt < 16; nt++) {
            const int c0 = nt * 8 + 2 * (lane & 3);
            float4 bw = *(const float4*)(smem + OFF_BW + c0 * 8);
            s0 = fmaf(gelu_f(acc[nt][0] + bw.x), bw.y, s0);
            s0 = fmaf(gelu_f(acc[nt][1] + bw.z), bw.w, s0);
            s1 = fmaf(gelu_f(acc[nt][2] + bw.x), bw.y, s1);
            s1 = fmaf(gelu_f(acc[nt][3] + bw.z), bw.w, s1);
        }
        s0 += __shfl_xor_sync(0xffffffffu, s0, 1);
        s0 += __shfl_xor_sync(0xffffffffu, s0, 2);
        s1 += __shfl_xor_sync(0xffffffffu, s1, 1);
        s1 += __shfl_xor_sync(0xffffffffu, s1, 2);
        if ((lane & 3) == 0) {
            const int t0 = tq * 16 + (lane >> 2);
            float* o = out + (size_t)b * (UU * TT) + u * TT;
            o[t0]     = s0 + bias3;
            o[t0 + 8] = s1 + bias3;
        }
    }
}

// ---------------------------------------------------------------------------
// Launch
// ---------------------------------------------------------------------------
extern "C" void kernel_launch(void* const* d_in, const int* in_sizes, int n_in,
                              void* d_out, int out_size) {
    (void)in_sizes; (void)n_in; (void)out_size;
    const float* ue = (const float*)d_in[0];
    const float* te = (const float*)d_in[1];
    const float* ge = (const float*)d_in[2];
    const float* W1 = (const float*)d_in[3];
    const float* b1 = (const float*)d_in[4];
    const float* W2 = (const float*)d_in[5];
    const float* b2 = (const float*)d_in[6];
    const float* W3 = (const float*)d_in[7];
    const float* b3 = (const float*)d_in[8];
    float* out = (float*)d_out;

    cudaFuncSetAttribute(pairwise_main,
                         cudaFuncAttributeMaxDynamicSharedMemorySize, SMEM_MAIN);

    prep_kernel<<<394, 128>>>(ue, te, ge, W1, b1, W2);
    pairwise_main<<<304, 256, SMEM_MAIN>>>(b2, W3, b3, out);
}